// round 14
// baseline (speedup 1.0000x reference)
#include <cuda_runtime.h>
#include <cuda_bf16.h>
#include <math.h>
#include <stdint.h>

#define NN 100000
#define EE 1600000
#define DIM 64
#define HEADS 8
#define HIDDEN 256
#define NB 391   // ceil(NN/256)
#define NTILES ((NN + 127) / 128)

// -------- scratch (device globals; no allocation allowed) --------
__device__ __align__(16) float g_h[NN * DIM];
__device__ __align__(16) float g_su[NN * HEADS];
__device__ __align__(16) float g_sv[NN * HEADS];
__device__ __align__(16) float g_aggr[NN * DIM];
__device__ float g_W2[2 * HEADS];
__device__ float g_c[HEADS];
__device__ int   g_deg[NN];
__device__ int   g_off[NN];
__device__ int   g_cur[NN];
__device__ int   g_bsum[512];
__device__ int   g_esrc[EE];
__device__ __align__(16) float g_esc[(size_t)EE * HEADS];  // exp'd scores per edge

// fast exp (FFMA-only)
__device__ __forceinline__ float fexp(float x) {
    float t = x * 1.4426950408889634f;
    int i = __float2int_rn(t);
    float f = t - (float)i;
    float g = f * 0.6931471805599453f;
    float p = 8.3333337676e-3f;
    p = fmaf(p, g, 4.1666668654e-2f);
    p = fmaf(p, g, 1.6666667163e-1f);
    p = fmaf(p, g, 5.0000000000e-1f);
    p = fmaf(p, g, 1.0f);
    p = fmaf(p, g, 1.0f);
    return __int_as_float(__float_as_int(p) + (i << 23));
}

__device__ __forceinline__ uint32_t to_tf32(float f) {
    uint32_t r;
    asm("cvt.rna.tf32.f32 %0, %1;" : "=r"(r) : "f"(f));
    return r;
}

// -------- tiny prep --------
__global__ void k_prep(const float* __restrict__ w_edge, const float* __restrict__ b_edge,
                       const float* __restrict__ w_att_e, const float* __restrict__ b_att_e) {
    int t = threadIdx.x;
    if (t < 16) {
        int i = t >> 3, hh = t & 7;
        float s = 0.f;
        for (int k = 0; k < DIM; k++) s = fmaf(w_edge[i * DIM + k], w_att_e[k * HEADS + hh], s);
        g_W2[t] = s;
    } else if (t < 24) {
        int hh = t - 16;
        float s = b_att_e[hh];
        for (int k = 0; k < DIM; k++) s = fmaf(b_edge[k], w_att_e[k * HEADS + hh], s);
        g_c[hh] = s;
    }
}

// -------- node input --------
__global__ __launch_bounds__(256) void k_node_in(
    const float* __restrict__ x, const float* __restrict__ w_in, const float* __restrict__ b_in,
    const float* __restrict__ wu, const float* __restrict__ bu, const float* __restrict__ wv) {
    __shared__ float xs[4 * DIM];
    __shared__ float hs[4 * DIM];
    __shared__ float wus[DIM * HEADS];
    __shared__ float wvs[DIM * HEADS];

    int t = threadIdx.x;
    int nd = t >> 6, j = t & 63;
    for (int i = t; i < DIM * HEADS; i += 256) { wus[i] = wu[i]; wvs[i] = wv[i]; }

    float wcol[DIM];
#pragma unroll
    for (int k = 0; k < DIM; k++) wcol[k] = w_in[k * DIM + j];
    float bj = b_in[j];
    __syncthreads();

    int ngroups = (NN + 3) / 4;
    for (int g = blockIdx.x; g < ngroups; g += gridDim.x) {
        int n = g * 4 + nd;
        if (n < NN) xs[nd * DIM + j] = x[n * DIM + j];
        __syncthreads();
        if (n < NN) {
            float acc = bj;
            const float4* xp = (const float4*)(xs + nd * DIM);
#pragma unroll
            for (int k4 = 0; k4 < 16; k4++) {
                float4 xv = xp[k4];
                acc = fmaf(xv.x, wcol[4 * k4 + 0], acc);
                acc = fmaf(xv.y, wcol[4 * k4 + 1], acc);
                acc = fmaf(xv.z, wcol[4 * k4 + 2], acc);
                acc = fmaf(xv.w, wcol[4 * k4 + 3], acc);
            }
            hs[nd * DIM + j] = acc;
            g_h[n * DIM + j] = acc;
        }
        __syncthreads();
        if (n < NN && j < 16) {
            int hh = j & 7;
            const float* wm = (j < 8) ? wus : wvs;
            float s = (j < 8) ? bu[hh] : 0.f;
#pragma unroll 8
            for (int k = 0; k < DIM; k++) s = fmaf(hs[nd * DIM + k], wm[k * HEADS + hh], s);
            if (j < 8) g_su[n * HEADS + hh] = s;
            else       g_sv[n * HEADS + hh] = s;
        }
        __syncthreads();
    }
}

// -------- CSR build --------
__global__ __launch_bounds__(256) void k_hist(const int* __restrict__ dst) {
    for (int e = blockIdx.x * 256 + threadIdx.x; e < EE; e += gridDim.x * 256)
        atomicAdd(&g_deg[dst[e]], 1);
}
__global__ __launch_bounds__(256) void k_scan_part() {
    __shared__ int s[256];
    int t = threadIdx.x;
    int i = blockIdx.x * 256 + t;
    s[t] = (i < NN) ? g_deg[i] : 0;
    __syncthreads();
    for (int ofs = 128; ofs > 0; ofs >>= 1) {
        if (t < ofs) s[t] += s[t + ofs];
        __syncthreads();
    }
    if (t == 0) g_bsum[blockIdx.x] = s[0];
}
__global__ __launch_bounds__(512) void k_scan_top() {
    __shared__ int s[512];
    int t = threadIdx.x;
    int v = (t < NB) ? g_bsum[t] : 0;
    s[t] = v;
    __syncthreads();
    for (int ofs = 1; ofs < 512; ofs <<= 1) {
        int add = (t >= ofs) ? s[t - ofs] : 0;
        __syncthreads();
        s[t] += add;
        __syncthreads();
    }
    if (t < NB) g_bsum[t] = s[t] - v;
}
__global__ __launch_bounds__(256) void k_scan_final() {
    __shared__ int s[256];
    int t = threadIdx.x;
    int i = blockIdx.x * 256 + t;
    int v = (i < NN) ? g_deg[i] : 0;
    s[t] = v;
    __syncthreads();
    for (int ofs = 1; ofs < 256; ofs <<= 1) {
        int add = (t >= ofs) ? s[t - ofs] : 0;
        __syncthreads();
        s[t] += add;
        __syncthreads();
    }
    if (i < NN) {
        int excl = s[t] - v + g_bsum[blockIdx.x];
        g_off[i] = excl;
        g_cur[i] = excl;
    }
}

// -------- scatter + per-edge score compute (thread-per-edge, 1x fexp work) --------
__global__ __launch_bounds__(256) void k_scatter_score(const int* __restrict__ src,
                                                       const int* __restrict__ dst,
                                                       const float* __restrict__ ef) {
    __shared__ float W2s[16];
    __shared__ float cs[8];
    if (threadIdx.x < 16) W2s[threadIdx.x] = g_W2[threadIdx.x];
    if (threadIdx.x < 8)  cs[threadIdx.x] = g_c[threadIdx.x];
    __syncthreads();

    for (int e = blockIdx.x * 256 + threadIdx.x; e < EE; e += gridDim.x * 256) {
        int s = src[e], d = dst[e];
        float2 f = ((const float2*)ef)[e];
        const float4* sup = (const float4*)(g_su + s * HEADS);
        const float4* svp = (const float4*)(g_sv + d * HEADS);
        float4 u0 = sup[0], u1 = sup[1], v0 = svp[0], v1 = svp[1];
        float tt[8];
        tt[0] = u0.x + v0.x; tt[1] = u0.y + v0.y; tt[2] = u0.z + v0.z; tt[3] = u0.w + v0.w;
        tt[4] = u1.x + v1.x; tt[5] = u1.y + v1.y; tt[6] = u1.z + v1.z; tt[7] = u1.w + v1.w;
#pragma unroll
        for (int hh = 0; hh < 8; hh++) {
            float v = tt[hh] + fmaf(f.x, W2s[hh], fmaf(f.y, W2s[8 + hh], cs[hh]));
            v = fmaxf(v, 0.2f * v);          // LeakyReLU(0.2)
            tt[hh] = fexp(v);
        }
        int p = atomicAdd(&g_cur[d], 1);
        g_esrc[p] = s;
        float4* op = (float4*)(g_esc + (size_t)p * 8);
        op[0] = make_float4(tt[0], tt[1], tt[2], tt[3]);
        op[1] = make_float4(tt[4], tt[5], tt[6], tt[7]);
    }
}

// -------- gather-aggregate: one warp per dst node; scores precomputed --------
__global__ __launch_bounds__(256) void k_aggr() {
    int n = (blockIdx.x * 256 + threadIdx.x) >> 5;
    if (n >= NN) return;
    int lane = threadIdx.x & 31;
    int hh = lane & 7;

    int beg = g_off[n], cnt = g_deg[n];

    float acc0 = 0.f, acc1 = 0.f, dsum = 0.f;
    if (cnt > 0) {
        int s0 = g_esrc[beg];
        float t0 = g_esc[(size_t)beg * 8 + hh];
        for (int it = 0; it < cnt; it++) {
            int s1 = 0; float t1 = 0.f;
            if (it + 1 < cnt) {
                s1 = g_esrc[beg + it + 1];
                t1 = g_esc[(size_t)(beg + it + 1) * 8 + hh];
            }
            dsum += t0;
            acc0 = fmaf(g_h[s0 * DIM + lane], t0, acc0);
            acc1 = fmaf(g_h[s0 * DIM + 32 + lane], t0, acc1);
            s0 = s1; t0 = t1;
        }
    }
    float inv = 1.f / fmaxf(dsum, 1e-12f);
    g_aggr[n * DIM + lane]      = acc0 * inv;
    g_aggr[n * DIM + 32 + lane] = acc1 * inv;
}

// ======== FFN via mma.sync tf32, two INDEPENDENT 256-thread halves per CTA ========
#define PA  68
#define PB2 260
#define OF_AH0 0
#define OF_AH1 (OF_AH0 + 128 * PA)
#define OF_B1  (OF_AH1 + 128 * PA)
#define OF_B2  (OF_B1 + 256 * PA)
#define OF_BV1 (OF_B2 + 64 * PB2)
#define OF_BV2 (OF_BV1 + 256)
#define SMF_TOTAL (OF_BV2 + 64)

#define MMA_TF32(c, a, b0v, b1v) \
    asm volatile("mma.sync.aligned.m16n8k8.row.col.f32.tf32.tf32.f32 " \
        "{%0,%1,%2,%3}, {%4,%5,%6,%7}, {%8,%9}, {%0,%1,%2,%3};" \
        : "+f"((c)[0]), "+f"((c)[1]), "+f"((c)[2]), "+f"((c)[3]) \
        : "r"((a)[0]), "r"((a)[1]), "r"((a)[2]), "r"((a)[3]), "r"(b0v), "r"(b1v))

#define BARH(id) asm volatile("bar.sync %0, %1;" :: "r"(id), "r"(256) : "memory")

__global__ __launch_bounds__(512, 1) void k_ffn_mma(
    const float* __restrict__ w1, const float* __restrict__ b1,
    const float* __restrict__ w2, const float* __restrict__ b2,
    float* __restrict__ out) {
    extern __shared__ float sm[];
    uint32_t* B1u = (uint32_t*)(sm + OF_B1);
    uint32_t* B2u = (uint32_t*)(sm + OF_B2);
    float* b1s = sm + OF_BV1;
    float* b2s = sm + OF_BV2;

    int t = threadIdx.x;
    int w = t >> 5, lane = t & 31;
    int gid = lane >> 2, tig = lane & 3;
    int half = w >> 3;
    int w8 = w & 7;
    int th = t & 255;
    int arow = w8 * 16 + gid;
    int barid = 1 + half;
    uint32_t* AHu = (uint32_t*)(sm + (half ? OF_AH1 : OF_AH0));

    if (t < 256) b1s[t] = b1[t];
    if (t < 64) b2s[t] = b2[t];
#pragma unroll
    for (int i = 0; i < 32; i++) {
        int idx = t + i * 512;
        int k = idx >> 8, n = idx & 255;
        B1u[n * PA + k] = to_tf32(w1[idx]);
    }
#pragma unroll
    for (int i = 0; i < 32; i++) {
        int idx = t + i * 512;
        int k = idx >> 6, n = idx & 63;
        B2u[n * PB2 + k] = to_tf32(w2[idx]);
    }
    __syncthreads();

    for (int tile = blockIdx.x * 2 + half; tile < NTILES; tile += gridDim.x * 2) {
        int n0 = tile * 128;
#pragma unroll
        for (int i = 0; i < 32; i++) {
            int idx = th + i * 256;
            int row = idx >> 6, kf = idx & 63;
            int node = n0 + row;
            float v = (node < NN) ? g_aggr[node * DIM + kf] : 0.f;
            AHu[row * PA + kf] = to_tf32(v);
        }
        BARH(barid);

        uint32_t af[8][4];
#pragma unroll
        for (int k = 0; k < 8; k++) {
            int base = arow * PA + k * 8 + tig;
            af[k][0] = AHu[base];
            af[k][1] = AHu[base + 8 * PA];
            af[k][2] = AHu[base + 4];
            af[k][3] = AHu[base + 8 * PA + 4];
        }
        BARH(barid);

        float c2[8][4];
#pragma unroll
        for (int nt = 0; nt < 8; nt++)
#pragma unroll
            for (int q = 0; q < 4; q++) c2[nt][q] = 0.f;

#pragma unroll
        for (int ch = 0; ch < 4; ch++) {
            int hc0 = ch * 64;
            float c1[8][4];
#pragma unroll
            for (int nt = 0; nt < 8; nt++)
#pragma unroll
                for (int q = 0; q < 4; q++) c1[nt][q] = 0.f;

#pragma unroll
            for (int nt = 0; nt < 8; nt++) {
                int nb = (hc0 + nt * 8 + gid) * PA + tig;
#pragma unroll
                for (int k = 0; k < 8; k++) {
                    uint32_t b0v = B1u[nb + k * 8];
                    uint32_t b1v = B1u[nb + k * 8 + 4];
                    MMA_TF32(c1[nt], af[k], b0v, b1v);
                }
            }
#pragma unroll
            for (int nt = 0; nt < 8; nt++) {
                int cl = nt * 8 + 2 * tig;
                int cg = hc0 + cl;
                float bb0 = b1s[cg], bb1 = b1s[cg + 1];
#pragma unroll
                for (int q = 0; q < 4; q++) {
                    int rr = arow + (q >> 1) * 8;
                    float v = c1[nt][q] + ((q & 1) ? bb1 : bb0);
                    v = 0.5f * v * (1.0f + erff(v * 0.70710678118654752f));
                    AHu[rr * PA + cl + (q & 1)] = to_tf32(v);
                }
            }
            BARH(barid);

#pragma unroll
            for (int k2 = 0; k2 < 8; k2++) {
                uint32_t a2[4];
                int base = arow * PA + k2 * 8 + tig;
                a2[0] = AHu[base];
                a2[1] = AHu[base + 8 * PA];
                a2[2] = AHu[base + 4];
                a2[3] = AHu[base + 8 * PA + 4];
#pragma unroll
                for (int nt = 0; nt < 8; nt++) {
                    int bb = (nt * 8 + gid) * PB2 + hc0 + k2 * 8 + tig;
                    uint32_t b0v = B2u[bb];
                    uint32_t b1v = B2u[bb + 4];
                    MMA_TF32(c2[nt], a2, b0v, b1v);
                }
            }
            BARH(barid);
        }

#pragma unroll
        for (int nt = 0; nt < 8; nt++) {
            int col = nt * 8 + 2 * tig;
            float bb0 = b2s[col], bb1 = b2s[col + 1];
            int nA = n0 + arow, nB = n0 + arow + 8;
            if (nA < NN) {
                float2 v = make_float2(c2[nt][0] + bb0, c2[nt][1] + bb1);
                *(float2*)(out + nA * DIM + col) = v;
            }
            if (nB < NN) {
                float2 v = make_float2(c2[nt][2] + bb0, c2[nt][3] + bb1);
                *(float2*)(out + nB * DIM + col) = v;
            }
        }
    }
}

extern "C" void kernel_launch(void* const* d_in, const int* in_sizes, int n_in,
                              void* d_out, int out_size) {
    const float* x       = (const float*)d_in[0];
    const float* ef      = (const float*)d_in[1];
    const float* w_in    = (const float*)d_in[2];
    const float* b_in    = (const float*)d_in[3];
    const float* w_edge  = (const float*)d_in[4];
    const float* b_edge  = (const float*)d_in[5];
    const float* w_att_u = (const float*)d_in[6];
    const float* b_att_u = (const float*)d_in[7];
    const float* w_att_v = (const float*)d_in[8];
    const float* w_att_e = (const float*)d_in[9];
    const float* b_att_e = (const float*)d_in[10];
    const float* w_ff1   = (const float*)d_in[11];
    const float* b_ff1   = (const float*)d_in[12];
    const float* w_ff2   = (const float*)d_in[13];
    const float* b_ff2   = (const float*)d_in[14];
    const int*   src     = (const int*)d_in[15];
    const int*   dst     = (const int*)d_in[16];
    float* out = (float*)d_out;

    cudaFuncSetAttribute(k_ffn_mma, cudaFuncAttributeMaxDynamicSharedMemorySize,
                         SMF_TOTAL * (int)sizeof(float));

    // one-time stream/event creation (host objects, not device memory)
    static cudaStream_t s_csr = nullptr;
    static cudaEvent_t ev_fork = nullptr, ev_join = nullptr;
    if (s_csr == nullptr) {
        cudaStreamCreateWithFlags(&s_csr, cudaStreamNonBlocking);
        cudaEventCreateWithFlags(&ev_fork, cudaEventDisableTiming);
        cudaEventCreateWithFlags(&ev_join, cudaEventDisableTiming);
    }

    void* p_deg = nullptr;
    cudaGetSymbolAddress(&p_deg, g_deg);

    // fork: CSR chain (hist+scans) on s_csr, node chain on stream 0
    cudaEventRecord(ev_fork, 0);
    cudaStreamWaitEvent(s_csr, ev_fork, 0);

    cudaMemsetAsync(p_deg, 0, (size_t)NN * sizeof(int), s_csr);
    k_hist<<<1184, 256, 0, s_csr>>>(dst);
    k_scan_part<<<NB, 256, 0, s_csr>>>();
    k_scan_top<<<1, 512, 0, s_csr>>>();
    k_scan_final<<<NB, 256, 0, s_csr>>>();
    cudaEventRecord(ev_join, s_csr);

    k_prep<<<1, 32>>>(w_edge, b_edge, w_att_e, b_att_e);
    k_node_in<<<2048, 256>>>(x, w_in, b_in, w_att_u, b_att_u, w_att_v);

    // join (scatter needs su/sv AND off/cur), then scatter+score, aggregate, FFN
    cudaStreamWaitEvent(0, ev_join, 0);
    k_scatter_score<<<1184, 256>>>(src, dst, ef);
    k_aggr<<<(NN * 32 + 255) / 256, 256>>>();
    k_ffn_mma<<<148, 512, SMF_TOTAL * sizeof(float)>>>(w_ff1, b_ff1, w_ff2, b_ff2, out);
}

// round 15
// speedup vs baseline: 1.1010x; 1.1010x over previous
#include <cuda_runtime.h>
#include <cuda_bf16.h>
#include <math.h>
#include <stdint.h>

#define NN 100000
#define EE 1600000
#define DIM 64
#define HEADS 8
#define HIDDEN 256
#define NB 391   // ceil(NN/256)
#define NTILES ((NN + 127) / 128)

// -------- scratch (device globals; no allocation allowed) --------
__device__ __align__(16) float g_h[NN * DIM];
__device__ __align__(16) float g_su[NN * HEADS];
__device__ __align__(16) float g_sv[NN * HEADS];
__device__ __align__(16) float g_aggr[NN * DIM];
__device__ float g_W2[2 * HEADS];
__device__ float g_c[HEADS];
__device__ int   g_deg[NN];
__device__ int   g_off[NN];
__device__ int   g_cur[NN];
__device__ int   g_bsum[512];
__device__ __align__(16) int4 g_edge[EE];   // {src, fx_bits, fy_bits, 0}

__device__ __forceinline__ uint32_t to_tf32(float f) {
    uint32_t r;
    asm("cvt.rna.tf32.f32 %0, %1;" : "=r"(r) : "f"(f));
    return r;
}

// -------- tiny prep --------
__global__ void k_prep(const float* __restrict__ w_edge, const float* __restrict__ b_edge,
                       const float* __restrict__ w_att_e, const float* __restrict__ b_att_e) {
    int t = threadIdx.x;
    if (t < 16) {
        int i = t >> 3, hh = t & 7;
        float s = 0.f;
        for (int k = 0; k < DIM; k++) s = fmaf(w_edge[i * DIM + k], w_att_e[k * HEADS + hh], s);
        g_W2[t] = s;
    } else if (t < 24) {
        int hh = t - 16;
        float s = b_att_e[hh];
        for (int k = 0; k < DIM; k++) s = fmaf(b_edge[k], w_att_e[k * HEADS + hh], s);
        g_c[hh] = s;
    }
}

// -------- node input --------
__global__ __launch_bounds__(256) void k_node_in(
    const float* __restrict__ x, const float* __restrict__ w_in, const float* __restrict__ b_in,
    const float* __restrict__ wu, const float* __restrict__ bu, const float* __restrict__ wv) {
    __shared__ float xs[4 * DIM];
    __shared__ float hs[4 * DIM];
    __shared__ float wus[DIM * HEADS];
    __shared__ float wvs[DIM * HEADS];

    int t = threadIdx.x;
    int nd = t >> 6, j = t & 63;
    for (int i = t; i < DIM * HEADS; i += 256) { wus[i] = wu[i]; wvs[i] = wv[i]; }

    float wcol[DIM];
#pragma unroll
    for (int k = 0; k < DIM; k++) wcol[k] = w_in[k * DIM + j];
    float bj = b_in[j];
    __syncthreads();

    int ngroups = (NN + 3) / 4;
    for (int g = blockIdx.x; g < ngroups; g += gridDim.x) {
        int n = g * 4 + nd;
        if (n < NN) xs[nd * DIM + j] = x[n * DIM + j];
        __syncthreads();
        if (n < NN) {
            float acc = bj;
            const float4* xp = (const float4*)(xs + nd * DIM);
#pragma unroll
            for (int k4 = 0; k4 < 16; k4++) {
                float4 xv = xp[k4];
                acc = fmaf(xv.x, wcol[4 * k4 + 0], acc);
                acc = fmaf(xv.y, wcol[4 * k4 + 1], acc);
                acc = fmaf(xv.z, wcol[4 * k4 + 2], acc);
                acc = fmaf(xv.w, wcol[4 * k4 + 3], acc);
            }
            hs[nd * DIM + j] = acc;
            g_h[n * DIM + j] = acc;
        }
        __syncthreads();
        if (n < NN && j < 16) {
            int hh = j & 7;
            const float* wm = (j < 8) ? wus : wvs;
            float s = (j < 8) ? bu[hh] : 0.f;
#pragma unroll 8
            for (int k = 0; k < DIM; k++) s = fmaf(hs[nd * DIM + k], wm[k * HEADS + hh], s);
            if (j < 8) g_su[n * HEADS + hh] = s;
            else       g_sv[n * HEADS + hh] = s;
        }
        __syncthreads();
    }
}

// -------- CSR build --------
__global__ __launch_bounds__(256) void k_hist(const int* __restrict__ dst) {
    for (int e = blockIdx.x * 256 + threadIdx.x; e < EE; e += gridDim.x * 256)
        atomicAdd(&g_deg[dst[e]], 1);
}
__global__ __launch_bounds__(256) void k_scan_part() {
    __shared__ int s[256];
    int t = threadIdx.x;
    int i = blockIdx.x * 256 + t;
    s[t] = (i < NN) ? g_deg[i] : 0;
    __syncthreads();
    for (int ofs = 128; ofs > 0; ofs >>= 1) {
        if (t < ofs) s[t] += s[t + ofs];
        __syncthreads();
    }
    if (t == 0) g_bsum[blockIdx.x] = s[0];
}
__global__ __launch_bounds__(512) void k_scan_top() {
    __shared__ int s[512];
    int t = threadIdx.x;
    int v = (t < NB) ? g_bsum[t] : 0;
    s[t] = v;
    __syncthreads();
    for (int ofs = 1; ofs < 512; ofs <<= 1) {
        int add = (t >= ofs) ? s[t - ofs] : 0;
        __syncthreads();
        s[t] += add;
        __syncthreads();
    }
    if (t < NB) g_bsum[t] = s[t] - v;
}
__global__ __launch_bounds__(256) void k_scan_final() {
    __shared__ int s[256];
    int t = threadIdx.x;
    int i = blockIdx.x * 256 + t;
    int v = (i < NN) ? g_deg[i] : 0;
    s[t] = v;
    __syncthreads();
    for (int ofs = 1; ofs < 256; ofs <<= 1) {
        int add = (t >= ofs) ? s[t - ofs] : 0;
        __syncthreads();
        s[t] += add;
        __syncthreads();
    }
    if (i < NN) {
        int excl = s[t] - v + g_bsum[blockIdx.x];
        g_off[i] = excl;
        g_cur[i] = excl;
    }
}
__global__ __launch_bounds__(256) void k_scatter(const int* __restrict__ src,
                                                const int* __restrict__ dst,
                                                const float* __restrict__ ef) {
    for (int e = blockIdx.x * 256 + threadIdx.x; e < EE; e += gridDim.x * 256) {
        int d = dst[e];
        float2 f = ((const float2*)ef)[e];
        int p = atomicAdd(&g_cur[d], 1);
        g_edge[p] = make_int4(src[e], __float_as_int(f.x), __float_as_int(f.y), 0);
    }
}

// -------- gather-aggregate: one warp per dst node (R11 loop shape,
//          packed int4 edge record + MUFU exp: strict issue-count cuts) --------
__global__ __launch_bounds__(256) void k_aggr() {
    int n = (blockIdx.x * 256 + threadIdx.x) >> 5;
    if (n >= NN) return;
    int lane = threadIdx.x & 31;
    int hh = lane & 7;

    float w2x = g_W2[hh], w2y = g_W2[8 + hh], cc = g_c[hh];
    float svv = g_sv[n * HEADS + hh];
    int beg = g_off[n], cnt = g_deg[n];

    float acc0 = 0.f, acc1 = 0.f, dsum = 0.f;
    if (cnt > 0) {
        int4 e0 = g_edge[beg];
        for (int it = 0; it < cnt; it++) {
            int4 e1 = make_int4(0, 0, 0, 0);
            if (it + 1 < cnt) e1 = g_edge[beg + it + 1];
            int s = e0.x;
            float fx = __int_as_float(e0.y), fy = __int_as_float(e0.z);
            float sc = g_su[s * HEADS + hh] + svv + fmaf(fx, w2x, fmaf(fy, w2y, cc));
            sc = fmaxf(sc, 0.2f * sc);       // LeakyReLU(0.2)
            float tt = __expf(sc);           // MUFU ex2: 2 issue slots vs 10 for poly
            dsum += tt;
            acc0 = fmaf(g_h[s * DIM + lane], tt, acc0);
            acc1 = fmaf(g_h[s * DIM + 32 + lane], tt, acc1);
            e0 = e1;
        }
    }
    float inv = 1.f / fmaxf(dsum, 1e-12f);
    g_aggr[n * DIM + lane]      = acc0 * inv;
    g_aggr[n * DIM + 32 + lane] = acc1 * inv;
}

// ======== FFN via mma.sync tf32, two INDEPENDENT 256-thread halves per CTA ========
#define PA  68
#define PB2 260
#define OF_AH0 0
#define OF_AH1 (OF_AH0 + 128 * PA)
#define OF_B1  (OF_AH1 + 128 * PA)
#define OF_B2  (OF_B1 + 256 * PA)
#define OF_BV1 (OF_B2 + 64 * PB2)
#define OF_BV2 (OF_BV1 + 256)
#define SMF_TOTAL (OF_BV2 + 64)

#define MMA_TF32(c, a, b0v, b1v) \
    asm volatile("mma.sync.aligned.m16n8k8.row.col.f32.tf32.tf32.f32 " \
        "{%0,%1,%2,%3}, {%4,%5,%6,%7}, {%8,%9}, {%0,%1,%2,%3};" \
        : "+f"((c)[0]), "+f"((c)[1]), "+f"((c)[2]), "+f"((c)[3]) \
        : "r"((a)[0]), "r"((a)[1]), "r"((a)[2]), "r"((a)[3]), "r"(b0v), "r"(b1v))

#define BARH(id) asm volatile("bar.sync %0, %1;" :: "r"(id), "r"(256) : "memory")

__global__ __launch_bounds__(512, 1) void k_ffn_mma(
    const float* __restrict__ w1, const float* __restrict__ b1,
    const float* __restrict__ w2, const float* __restrict__ b2,
    float* __restrict__ out) {
    extern __shared__ float sm[];
    uint32_t* B1u = (uint32_t*)(sm + OF_B1);
    uint32_t* B2u = (uint32_t*)(sm + OF_B2);
    float* b1s = sm + OF_BV1;
    float* b2s = sm + OF_BV2;

    int t = threadIdx.x;
    int w = t >> 5, lane = t & 31;
    int gid = lane >> 2, tig = lane & 3;
    int half = w >> 3;
    int w8 = w & 7;
    int th = t & 255;
    int arow = w8 * 16 + gid;
    int barid = 1 + half;
    uint32_t* AHu = (uint32_t*)(sm + (half ? OF_AH1 : OF_AH0));

    if (t < 256) b1s[t] = b1[t];
    if (t < 64) b2s[t] = b2[t];
#pragma unroll
    for (int i = 0; i < 32; i++) {
        int idx = t + i * 512;
        int k = idx >> 8, n = idx & 255;
        B1u[n * PA + k] = to_tf32(w1[idx]);
    }
#pragma unroll
    for (int i = 0; i < 32; i++) {
        int idx = t + i * 512;
        int k = idx >> 6, n = idx & 63;
        B2u[n * PB2 + k] = to_tf32(w2[idx]);
    }
    __syncthreads();

    for (int tile = blockIdx.x * 2 + half; tile < NTILES; tile += gridDim.x * 2) {
        int n0 = tile * 128;
#pragma unroll
        for (int i = 0; i < 32; i++) {
            int idx = th + i * 256;
            int row = idx >> 6, kf = idx & 63;
            int node = n0 + row;
            float v = (node < NN) ? g_aggr[node * DIM + kf] : 0.f;
            AHu[row * PA + kf] = to_tf32(v);
        }
        BARH(barid);

        uint32_t af[8][4];
#pragma unroll
        for (int k = 0; k < 8; k++) {
            int base = arow * PA + k * 8 + tig;
            af[k][0] = AHu[base];
            af[k][1] = AHu[base + 8 * PA];
            af[k][2] = AHu[base + 4];
            af[k][3] = AHu[base + 8 * PA + 4];
        }
        BARH(barid);

        float c2[8][4];
#pragma unroll
        for (int nt = 0; nt < 8; nt++)
#pragma unroll
            for (int q = 0; q < 4; q++) c2[nt][q] = 0.f;

#pragma unroll
        for (int ch = 0; ch < 4; ch++) {
            int hc0 = ch * 64;
            float c1[8][4];
#pragma unroll
            for (int nt = 0; nt < 8; nt++)
#pragma unroll
                for (int q = 0; q < 4; q++) c1[nt][q] = 0.f;

#pragma unroll
            for (int nt = 0; nt < 8; nt++) {
                int nb = (hc0 + nt * 8 + gid) * PA + tig;
#pragma unroll
                for (int k = 0; k < 8; k++) {
                    uint32_t b0v = B1u[nb + k * 8];
                    uint32_t b1v = B1u[nb + k * 8 + 4];
                    MMA_TF32(c1[nt], af[k], b0v, b1v);
                }
            }
#pragma unroll
            for (int nt = 0; nt < 8; nt++) {
                int cl = nt * 8 + 2 * tig;
                int cg = hc0 + cl;
                float bb0 = b1s[cg], bb1 = b1s[cg + 1];
#pragma unroll
                for (int q = 0; q < 4; q++) {
                    int rr = arow + (q >> 1) * 8;
                    float v = c1[nt][q] + ((q & 1) ? bb1 : bb0);
                    v = 0.5f * v * (1.0f + erff(v * 0.70710678118654752f));
                    AHu[rr * PA + cl + (q & 1)] = to_tf32(v);
                }
            }
            BARH(barid);

#pragma unroll
            for (int k2 = 0; k2 < 8; k2++) {
                uint32_t a2[4];
                int base = arow * PA + k2 * 8 + tig;
                a2[0] = AHu[base];
                a2[1] = AHu[base + 8 * PA];
                a2[2] = AHu[base + 4];
                a2[3] = AHu[base + 8 * PA + 4];
#pragma unroll
                for (int nt = 0; nt < 8; nt++) {
                    int bb = (nt * 8 + gid) * PB2 + hc0 + k2 * 8 + tig;
                    uint32_t b0v = B2u[bb];
                    uint32_t b1v = B2u[bb + 4];
                    MMA_TF32(c2[nt], a2, b0v, b1v);
                }
            }
            BARH(barid);
        }

#pragma unroll
        for (int nt = 0; nt < 8; nt++) {
            int col = nt * 8 + 2 * tig;
            float bb0 = b2s[col], bb1 = b2s[col + 1];
            int nA = n0 + arow, nB = n0 + arow + 8;
            if (nA < NN) {
                float2 v = make_float2(c2[nt][0] + bb0, c2[nt][1] + bb1);
                *(float2*)(out + nA * DIM + col) = v;
            }
            if (nB < NN) {
                float2 v = make_float2(c2[nt][2] + bb0, c2[nt][3] + bb1);
                *(float2*)(out + nB * DIM + col) = v;
            }
        }
    }
}

extern "C" void kernel_launch(void* const* d_in, const int* in_sizes, int n_in,
                              void* d_out, int out_size) {
    const float* x       = (const float*)d_in[0];
    const float* ef      = (const float*)d_in[1];
    const float* w_in    = (const float*)d_in[2];
    const float* b_in    = (const float*)d_in[3];
    const float* w_edge  = (const float*)d_in[4];
    const float* b_edge  = (const float*)d_in[5];
    const float* w_att_u = (const float*)d_in[6];
    const float* b_att_u = (const float*)d_in[7];
    const float* w_att_v = (const float*)d_in[8];
    const float* w_att_e = (const float*)d_in[9];
    const float* b_att_e = (const float*)d_in[10];
    const float* w_ff1   = (const float*)d_in[11];
    const float* b_ff1   = (const float*)d_in[12];
    const float* w_ff2   = (const float*)d_in[13];
    const float* b_ff2   = (const float*)d_in[14];
    const int*   src     = (const int*)d_in[15];
    const int*   dst     = (const int*)d_in[16];
    float* out = (float*)d_out;

    cudaFuncSetAttribute(k_ffn_mma, cudaFuncAttributeMaxDynamicSharedMemorySize,
                         SMF_TOTAL * (int)sizeof(float));

    // one-time stream/event creation (host objects, not device memory)
    static cudaStream_t s_csr = nullptr;
    static cudaEvent_t ev_fork = nullptr, ev_join = nullptr;
    if (s_csr == nullptr) {
        cudaStreamCreateWithFlags(&s_csr, cudaStreamNonBlocking);
        cudaEventCreateWithFlags(&ev_fork, cudaEventDisableTiming);
        cudaEventCreateWithFlags(&ev_join, cudaEventDisableTiming);
    }

    void* p_deg = nullptr;
    cudaGetSymbolAddress(&p_deg, g_deg);

    // fork: CSR chain on s_csr, node chain on stream 0
    cudaEventRecord(ev_fork, 0);
    cudaStreamWaitEvent(s_csr, ev_fork, 0);

    cudaMemsetAsync(p_deg, 0, (size_t)NN * sizeof(int), s_csr);
    k_hist<<<1184, 256, 0, s_csr>>>(dst);
    k_scan_part<<<NB, 256, 0, s_csr>>>();
    k_scan_top<<<1, 512, 0, s_csr>>>();
    k_scan_final<<<NB, 256, 0, s_csr>>>();
    k_scatter<<<1184, 256, 0, s_csr>>>(src, dst, ef);
    cudaEventRecord(ev_join, s_csr);

    k_prep<<<1, 32>>>(w_edge, b_edge, w_att_e, b_att_e);
    k_node_in<<<2048, 256>>>(x, w_in, b_in, w_att_u, b_att_u, w_att_v);

    // join, then aggregate + FFN
    cudaStreamWaitEvent(0, ev_join, 0);
    k_aggr<<<(NN * 32 + 255) / 256, 256>>>();
    k_ffn_mma<<<148, 512, SMF_TOTAL * sizeof(float)>>>(w_ff1, b_ff1, w_ff2, b_ff2, out);
}

// round 16
// speedup vs baseline: 1.1077x; 1.0061x over previous
#include <cuda_runtime.h>
#include <cuda_bf16.h>
#include <math.h>
#include <stdint.h>

#define NN 100000
#define EE 1600000
#define DIM 64
#define HEADS 8
#define HIDDEN 256
#define NB 391   // ceil(NN/256)
#define NTILES ((NN + 127) / 128)

// -------- scratch (device globals; no allocation allowed) --------
__device__ __align__(16) float g_h[NN * DIM];
__device__ __align__(16) float g_su[NN * HEADS];
__device__ __align__(16) float g_sv[NN * HEADS];
__device__ __align__(16) float g_aggr[NN * DIM];
__device__ float g_W2[2 * HEADS];
__device__ float g_c[HEADS];
__device__ int   g_deg[NN];     // zero at entry of each run (zero-on-consume in k_aggr)
__device__ int   g_off[NN];
__device__ int   g_cur[NN];
__device__ int   g_base_ctr;    // scan base counter (reset by k_scatter for next run)
__device__ __align__(16) int4 g_edge[EE];   // {src, fx_bits, fy_bits, 0}

__device__ __forceinline__ uint32_t to_tf32(float f) {
    uint32_t r;
    asm("cvt.rna.tf32.f32 %0, %1;" : "=r"(r) : "f"(f));
    return r;
}

// -------- tiny prep --------
__global__ void k_prep(const float* __restrict__ w_edge, const float* __restrict__ b_edge,
                       const float* __restrict__ w_att_e, const float* __restrict__ b_att_e) {
    int t = threadIdx.x;
    if (t < 16) {
        int i = t >> 3, hh = t & 7;
        float s = 0.f;
        for (int k = 0; k < DIM; k++) s = fmaf(w_edge[i * DIM + k], w_att_e[k * HEADS + hh], s);
        g_W2[t] = s;
    } else if (t < 24) {
        int hh = t - 16;
        float s = b_att_e[hh];
        for (int k = 0; k < DIM; k++) s = fmaf(b_edge[k], w_att_e[k * HEADS + hh], s);
        g_c[hh] = s;
    }
}

// -------- node input --------
__global__ __launch_bounds__(256) void k_node_in(
    const float* __restrict__ x, const float* __restrict__ w_in, const float* __restrict__ b_in,
    const float* __restrict__ wu, const float* __restrict__ bu, const float* __restrict__ wv) {
    __shared__ float xs[4 * DIM];
    __shared__ float hs[4 * DIM];
    __shared__ float wus[DIM * HEADS];
    __shared__ float wvs[DIM * HEADS];

    int t = threadIdx.x;
    int nd = t >> 6, j = t & 63;
    for (int i = t; i < DIM * HEADS; i += 256) { wus[i] = wu[i]; wvs[i] = wv[i]; }

    float wcol[DIM];
#pragma unroll
    for (int k = 0; k < DIM; k++) wcol[k] = w_in[k * DIM + j];
    float bj = b_in[j];
    __syncthreads();

    int ngroups = (NN + 3) / 4;
    for (int g = blockIdx.x; g < ngroups; g += gridDim.x) {
        int n = g * 4 + nd;
        if (n < NN) xs[nd * DIM + j] = x[n * DIM + j];
        __syncthreads();
        if (n < NN) {
            float acc = bj;
            const float4* xp = (const float4*)(xs + nd * DIM);
#pragma unroll
            for (int k4 = 0; k4 < 16; k4++) {
                float4 xv = xp[k4];
                acc = fmaf(xv.x, wcol[4 * k4 + 0], acc);
                acc = fmaf(xv.y, wcol[4 * k4 + 1], acc);
                acc = fmaf(xv.z, wcol[4 * k4 + 2], acc);
                acc = fmaf(xv.w, wcol[4 * k4 + 3], acc);
            }
            hs[nd * DIM + j] = acc;
            g_h[n * DIM + j] = acc;
        }
        __syncthreads();
        if (n < NN && j < 16) {
            int hh = j & 7;
            const float* wm = (j < 8) ? wus : wvs;
            float s = (j < 8) ? bu[hh] : 0.f;
#pragma unroll 8
            for (int k = 0; k < DIM; k++) s = fmaf(hs[nd * DIM + k], wm[k * HEADS + hh], s);
            if (j < 8) g_su[n * HEADS + hh] = s;
            else       g_sv[n * HEADS + hh] = s;
        }
        __syncthreads();
    }
}

// -------- CSR build: hist -> single-launch scan -> scatter --------
__global__ __launch_bounds__(256) void k_hist(const int* __restrict__ dst) {
    for (int e = blockIdx.x * 256 + threadIdx.x; e < EE; e += gridDim.x * 256)
        atomicAdd(&g_deg[dst[e]], 1);
}

// One-launch scan: per-block inclusive scan + atomic base grab.
// Segment placement order across blocks is arbitrary — CSR only needs disjoint segments.
__global__ __launch_bounds__(256) void k_scan_one() {
    __shared__ int s[256];
    __shared__ int base_sh;
    int t = threadIdx.x;
    int i = blockIdx.x * 256 + t;
    int v = (i < NN) ? g_deg[i] : 0;
    s[t] = v;
    __syncthreads();
    for (int ofs = 1; ofs < 256; ofs <<= 1) {
        int add = (t >= ofs) ? s[t - ofs] : 0;
        __syncthreads();
        s[t] += add;
        __syncthreads();
    }
    if (t == 255) base_sh = atomicAdd(&g_base_ctr, s[255]);
    __syncthreads();
    if (i < NN) {
        int excl = s[t] - v + base_sh;
        g_off[i] = excl;
        g_cur[i] = excl;
    }
}

__global__ __launch_bounds__(256) void k_scatter(const int* __restrict__ src,
                                                const int* __restrict__ dst,
                                                const float* __restrict__ ef) {
    // reset scan base counter for the next run (scan has already completed)
    if (blockIdx.x == 0 && threadIdx.x == 0) g_base_ctr = 0;
    for (int e = blockIdx.x * 256 + threadIdx.x; e < EE; e += gridDim.x * 256) {
        int d = dst[e];
        float2 f = ((const float2*)ef)[e];
        int p = atomicAdd(&g_cur[d], 1);
        g_edge[p] = make_int4(src[e], __float_as_int(f.x), __float_as_int(f.y), 0);
    }
}

// -------- gather-aggregate: one warp per dst node (R15 proven loop) --------
// Zero-on-consume: clears g_deg[n] for the next run (no memset launch).
__global__ __launch_bounds__(256) void k_aggr() {
    int n = (blockIdx.x * 256 + threadIdx.x) >> 5;
    if (n >= NN) return;
    int lane = threadIdx.x & 31;
    int hh = lane & 7;

    float w2x = g_W2[hh], w2y = g_W2[8 + hh], cc = g_c[hh];
    float svv = g_sv[n * HEADS + hh];
    int beg = g_off[n], cnt = g_deg[n];

    float acc0 = 0.f, acc1 = 0.f, dsum = 0.f;
    if (cnt > 0) {
        int4 e0 = g_edge[beg];
        for (int it = 0; it < cnt; it++) {
            int4 e1 = make_int4(0, 0, 0, 0);
            if (it + 1 < cnt) e1 = g_edge[beg + it + 1];
            int s = e0.x;
            float fx = __int_as_float(e0.y), fy = __int_as_float(e0.z);
            float sc = g_su[s * HEADS + hh] + svv + fmaf(fx, w2x, fmaf(fy, w2y, cc));
            sc = fmaxf(sc, 0.2f * sc);       // LeakyReLU(0.2)
            float tt = __expf(sc);
            dsum += tt;
            acc0 = fmaf(g_h[s * DIM + lane], tt, acc0);
            acc1 = fmaf(g_h[s * DIM + 32 + lane], tt, acc1);
            e0 = e1;
        }
    }
    float inv = 1.f / fmaxf(dsum, 1e-12f);
    g_aggr[n * DIM + lane]      = acc0 * inv;
    g_aggr[n * DIM + 32 + lane] = acc1 * inv;
    if (lane == 0) g_deg[n] = 0;   // zero-on-consume for next run
}

// ======== FFN via mma.sync tf32, two INDEPENDENT 256-thread halves per CTA ========
#define PA  68
#define PB2 260
#define OF_AH0 0
#define OF_AH1 (OF_AH0 + 128 * PA)
#define OF_B1  (OF_AH1 + 128 * PA)
#define OF_B2  (OF_B1 + 256 * PA)
#define OF_BV1 (OF_B2 + 64 * PB2)
#define OF_BV2 (OF_BV1 + 256)
#define SMF_TOTAL (OF_BV2 + 64)

#define MMA_TF32(c, a, b0v, b1v) \
    asm volatile("mma.sync.aligned.m16n8k8.row.col.f32.tf32.tf32.f32 " \
        "{%0,%1,%2,%3}, {%4,%5,%6,%7}, {%8,%9}, {%0,%1,%2,%3};" \
        : "+f"((c)[0]), "+f"((c)[1]), "+f"((c)[2]), "+f"((c)[3]) \
        : "r"((a)[0]), "r"((a)[1]), "r"((a)[2]), "r"((a)[3]), "r"(b0v), "r"(b1v))

#define BARH(id) asm volatile("bar.sync %0, %1;" :: "r"(id), "r"(256) : "memory")

__global__ __launch_bounds__(512, 1) void k_ffn_mma(
    const float* __restrict__ w1, const float* __restrict__ b1,
    const float* __restrict__ w2, const float* __restrict__ b2,
    float* __restrict__ out) {
    extern __shared__ float sm[];
    uint32_t* B1u = (uint32_t*)(sm + OF_B1);
    uint32_t* B2u = (uint32_t*)(sm + OF_B2);
    float* b1s = sm + OF_BV1;
    float* b2s = sm + OF_BV2;

    int t = threadIdx.x;
    int w = t >> 5, lane = t & 31;
    int gid = lane >> 2, tig = lane & 3;
    int half = w >> 3;
    int w8 = w & 7;
    int th = t & 255;
    int arow = w8 * 16 + gid;
    int barid = 1 + half;
    uint32_t* AHu = (uint32_t*)(sm + (half ? OF_AH1 : OF_AH0));

    if (t < 256) b1s[t] = b1[t];
    if (t < 64) b2s[t] = b2[t];
#pragma unroll
    for (int i = 0; i < 32; i++) {
        int idx = t + i * 512;
        int k = idx >> 8, n = idx & 255;
        B1u[n * PA + k] = to_tf32(w1[idx]);
    }
#pragma unroll
    for (int i = 0; i < 32; i++) {
        int idx = t + i * 512;
        int k = idx >> 6, n = idx & 63;
        B2u[n * PB2 + k] = to_tf32(w2[idx]);
    }
    __syncthreads();

    for (int tile = blockIdx.x * 2 + half; tile < NTILES; tile += gridDim.x * 2) {
        int n0 = tile * 128;
#pragma unroll
        for (int i = 0; i < 32; i++) {
            int idx = th + i * 256;
            int row = idx >> 6, kf = idx & 63;
            int node = n0 + row;
            float v = (node < NN) ? g_aggr[node * DIM + kf] : 0.f;
            AHu[row * PA + kf] = to_tf32(v);
        }
        BARH(barid);

        uint32_t af[8][4];
#pragma unroll
        for (int k = 0; k < 8; k++) {
            int base = arow * PA + k * 8 + tig;
            af[k][0] = AHu[base];
            af[k][1] = AHu[base + 8 * PA];
            af[k][2] = AHu[base + 4];
            af[k][3] = AHu[base + 8 * PA + 4];
        }
        BARH(barid);

        float c2[8][4];
#pragma unroll
        for (int nt = 0; nt < 8; nt++)
#pragma unroll
            for (int q = 0; q < 4; q++) c2[nt][q] = 0.f;

#pragma unroll
        for (int ch = 0; ch < 4; ch++) {
            int hc0 = ch * 64;
            float c1[8][4];
#pragma unroll
            for (int nt = 0; nt < 8; nt++)
#pragma unroll
                for (int q = 0; q < 4; q++) c1[nt][q] = 0.f;

#pragma unroll
            for (int nt = 0; nt < 8; nt++) {
                int nb = (hc0 + nt * 8 + gid) * PA + tig;
#pragma unroll
                for (int k = 0; k < 8; k++) {
                    uint32_t b0v = B1u[nb + k * 8];
                    uint32_t b1v = B1u[nb + k * 8 + 4];
                    MMA_TF32(c1[nt], af[k], b0v, b1v);
                }
            }
#pragma unroll
            for (int nt = 0; nt < 8; nt++) {
                int cl = nt * 8 + 2 * tig;
                int cg = hc0 + cl;
                float bb0 = b1s[cg], bb1 = b1s[cg + 1];
#pragma unroll
                for (int q = 0; q < 4; q++) {
                    int rr = arow + (q >> 1) * 8;
                    float v = c1[nt][q] + ((q & 1) ? bb1 : bb0);
                    v = 0.5f * v * (1.0f + erff(v * 0.70710678118654752f));
                    AHu[rr * PA + cl + (q & 1)] = to_tf32(v);
                }
            }
            BARH(barid);

#pragma unroll
            for (int k2 = 0; k2 < 8; k2++) {
                uint32_t a2[4];
                int base = arow * PA + k2 * 8 + tig;
                a2[0] = AHu[base];
                a2[1] = AHu[base + 8 * PA];
                a2[2] = AHu[base + 4];
                a2[3] = AHu[base + 8 * PA + 4];
#pragma unroll
                for (int nt = 0; nt < 8; nt++) {
                    int bb = (nt * 8 + gid) * PB2 + hc0 + k2 * 8 + tig;
                    uint32_t b0v = B2u[bb];
                    uint32_t b1v = B2u[bb + 4];
                    MMA_TF32(c2[nt], a2, b0v, b1v);
                }
            }
            BARH(barid);
        }

#pragma unroll
        for (int nt = 0; nt < 8; nt++) {
            int col = nt * 8 + 2 * tig;
            float bb0 = b2s[col], bb1 = b2s[col + 1];
            int nA = n0 + arow, nB = n0 + arow + 8;
            if (nA < NN) {
                float2 v = make_float2(c2[nt][0] + bb0, c2[nt][1] + bb1);
                *(float2*)(out + nA * DIM + col) = v;
            }
            if (nB < NN) {
                float2 v = make_float2(c2[nt][2] + bb0, c2[nt][3] + bb1);
                *(float2*)(out + nB * DIM + col) = v;
            }
        }
    }
}

extern "C" void kernel_launch(void* const* d_in, const int* in_sizes, int n_in,
                              void* d_out, int out_size) {
    const float* x       = (const float*)d_in[0];
    const float* ef      = (const float*)d_in[1];
    const float* w_in    = (const float*)d_in[2];
    const float* b_in    = (const float*)d_in[3];
    const float* w_edge  = (const float*)d_in[4];
    const float* b_edge  = (const float*)d_in[5];
    const float* w_att_u = (const float*)d_in[6];
    const float* b_att_u = (const float*)d_in[7];
    const float* w_att_v = (const float*)d_in[8];
    const float* w_att_e = (const float*)d_in[9];
    const float* b_att_e = (const float*)d_in[10];
    const float* w_ff1   = (const float*)d_in[11];
    const float* b_ff1   = (const float*)d_in[12];
    const float* w_ff2   = (const float*)d_in[13];
    const float* b_ff2   = (const float*)d_in[14];
    const int*   src     = (const int*)d_in[15];
    const int*   dst     = (const int*)d_in[16];
    float* out = (float*)d_out;

    cudaFuncSetAttribute(k_ffn_mma, cudaFuncAttributeMaxDynamicSharedMemorySize,
                         SMF_TOTAL * (int)sizeof(float));

    // one-time stream/event creation (host objects, not device memory)
    static cudaStream_t s_csr = nullptr;
    static cudaEvent_t ev_fork = nullptr, ev_join = nullptr;
    if (s_csr == nullptr) {
        cudaStreamCreateWithFlags(&s_csr, cudaStreamNonBlocking);
        cudaEventCreateWithFlags(&ev_fork, cudaEventDisableTiming);
        cudaEventCreateWithFlags(&ev_join, cudaEventDisableTiming);
    }

    // fork: CSR chain on s_csr (3 launches), node chain on stream 0
    cudaEventRecord(ev_fork, 0);
    cudaStreamWaitEvent(s_csr, ev_fork, 0);

    k_hist<<<1184, 256, 0, s_csr>>>(dst);           // g_deg zeroed by prior k_aggr
    k_scan_one<<<NB, 256, 0, s_csr>>>();            // single-launch scan (atomic base)
    k_scatter<<<1184, 256, 0, s_csr>>>(src, dst, ef);  // also resets g_base_ctr
    cudaEventRecord(ev_join, s_csr);

    k_prep<<<1, 32>>>(w_edge, b_edge, w_att_e, b_att_e);
    k_node_in<<<2048, 256>>>(x, w_in, b_in, w_att_u, b_att_u, w_att_v);

    // join, then aggregate + FFN
    cudaStreamWaitEvent(0, ev_join, 0);
    k_aggr<<<(NN * 32 + 255) / 256, 256>>>();
    k_ffn_mma<<<148, 512, SMF_TOTAL * sizeof(float)>>>(w_ff1, b_ff1, w_ff2, b_ff2, out);
}

// round 17
// speedup vs baseline: 1.1322x; 1.0221x over previous
#include <cuda_runtime.h>
#include <cuda_bf16.h>
#include <math.h>
#include <stdint.h>

#define NN 100000
#define EE 1600000
#define DIM 64
#define HEADS 8
#define HIDDEN 256
#define NB 391   // ceil(NN/256)
#define NTILES ((NN + 127) / 128)

// -------- scratch (device globals; no allocation allowed) --------
__device__ __align__(16) float g_h[NN * DIM];
__device__ __align__(16) float g_su[NN * HEADS];
__device__ __align__(16) float g_sv[NN * HEADS];
__device__ __align__(16) float g_aggr[NN * DIM];
__device__ float g_W2[2 * HEADS];
__device__ float g_c[HEADS];
__device__ int   g_deg[NN];     // zero at entry of each run (zero-on-consume in k_aggr)
__device__ int   g_off[NN];
__device__ int   g_cur[NN];
__device__ int   g_base_ctr;    // scan base counter (reset by k_scatter)
__device__ int   g_work;        // aggr work cursor (reset by k_scatter)
__device__ __align__(16) int4 g_edge[EE];   // {src, fx_bits, fy_bits, 0}

__device__ __forceinline__ uint32_t to_tf32(float f) {
    uint32_t r;
    asm("cvt.rna.tf32.f32 %0, %1;" : "=r"(r) : "f"(f));
    return r;
}

// -------- tiny prep --------
__global__ void k_prep(const float* __restrict__ w_edge, const float* __restrict__ b_edge,
                       const float* __restrict__ w_att_e, const float* __restrict__ b_att_e) {
    int t = threadIdx.x;
    if (t < 16) {
        int i = t >> 3, hh = t & 7;
        float s = 0.f;
        for (int k = 0; k < DIM; k++) s = fmaf(w_edge[i * DIM + k], w_att_e[k * HEADS + hh], s);
        g_W2[t] = s;
    } else if (t < 24) {
        int hh = t - 16;
        float s = b_att_e[hh];
        for (int k = 0; k < DIM; k++) s = fmaf(b_edge[k], w_att_e[k * HEADS + hh], s);
        g_c[hh] = s;
    }
}

// -------- node input --------
__global__ __launch_bounds__(256) void k_node_in(
    const float* __restrict__ x, const float* __restrict__ w_in, const float* __restrict__ b_in,
    const float* __restrict__ wu, const float* __restrict__ bu, const float* __restrict__ wv) {
    __shared__ float xs[4 * DIM];
    __shared__ float hs[4 * DIM];
    __shared__ float wus[DIM * HEADS];
    __shared__ float wvs[DIM * HEADS];

    int t = threadIdx.x;
    int nd = t >> 6, j = t & 63;
    for (int i = t; i < DIM * HEADS; i += 256) { wus[i] = wu[i]; wvs[i] = wv[i]; }

    float wcol[DIM];
#pragma unroll
    for (int k = 0; k < DIM; k++) wcol[k] = w_in[k * DIM + j];
    float bj = b_in[j];
    __syncthreads();

    int ngroups = (NN + 3) / 4;
    for (int g = blockIdx.x; g < ngroups; g += gridDim.x) {
        int n = g * 4 + nd;
        if (n < NN) xs[nd * DIM + j] = x[n * DIM + j];
        __syncthreads();
        if (n < NN) {
            float acc = bj;
            const float4* xp = (const float4*)(xs + nd * DIM);
#pragma unroll
            for (int k4 = 0; k4 < 16; k4++) {
                float4 xv = xp[k4];
                acc = fmaf(xv.x, wcol[4 * k4 + 0], acc);
                acc = fmaf(xv.y, wcol[4 * k4 + 1], acc);
                acc = fmaf(xv.z, wcol[4 * k4 + 2], acc);
                acc = fmaf(xv.w, wcol[4 * k4 + 3], acc);
            }
            hs[nd * DIM + j] = acc;
            g_h[n * DIM + j] = acc;
        }
        __syncthreads();
        if (n < NN && j < 16) {
            int hh = j & 7;
            const float* wm = (j < 8) ? wus : wvs;
            float s = (j < 8) ? bu[hh] : 0.f;
#pragma unroll 8
            for (int k = 0; k < DIM; k++) s = fmaf(hs[nd * DIM + k], wm[k * HEADS + hh], s);
            if (j < 8) g_su[n * HEADS + hh] = s;
            else       g_sv[n * HEADS + hh] = s;
        }
        __syncthreads();
    }
}

// -------- CSR build: hist -> single-launch scan -> scatter --------
__global__ __launch_bounds__(256) void k_hist(const int* __restrict__ dst) {
    for (int e = blockIdx.x * 256 + threadIdx.x; e < EE; e += gridDim.x * 256)
        atomicAdd(&g_deg[dst[e]], 1);
}

__global__ __launch_bounds__(256) void k_scan_one() {
    __shared__ int s[256];
    __shared__ int base_sh;
    int t = threadIdx.x;
    int i = blockIdx.x * 256 + t;
    int v = (i < NN) ? g_deg[i] : 0;
    s[t] = v;
    __syncthreads();
    for (int ofs = 1; ofs < 256; ofs <<= 1) {
        int add = (t >= ofs) ? s[t - ofs] : 0;
        __syncthreads();
        s[t] += add;
        __syncthreads();
    }
    if (t == 255) base_sh = atomicAdd(&g_base_ctr, s[255]);
    __syncthreads();
    if (i < NN) {
        int excl = s[t] - v + base_sh;
        g_off[i] = excl;
        g_cur[i] = excl;
    }
}

__global__ __launch_bounds__(256) void k_scatter(const int* __restrict__ src,
                                                const int* __restrict__ dst,
                                                const float* __restrict__ ef) {
    if (blockIdx.x == 0 && threadIdx.x == 0) { g_base_ctr = 0; g_work = 0; }
    for (int e = blockIdx.x * 256 + threadIdx.x; e < EE; e += gridDim.x * 256) {
        int d = dst[e];
        float2 f = ((const float2*)ef)[e];
        int p = atomicAdd(&g_cur[d], 1);
        g_edge[p] = make_int4(src[e], __float_as_int(f.x), __float_as_int(f.y), 0);
    }
}

// -------- gather-aggregate: dynamic work-stealing warps (R15 inner loop) --------
#define AGGR_BATCH 4
__global__ __launch_bounds__(256) void k_aggr() {
    int lane = threadIdx.x & 31;
    int hh = lane & 7;
    float w2x = g_W2[hh], w2y = g_W2[8 + hh], cc = g_c[hh];

    for (;;) {
        int base = 0;
        if (lane == 0) base = atomicAdd(&g_work, AGGR_BATCH);
        base = __shfl_sync(0xffffffffu, base, 0);
        if (base >= NN) break;
        int nend = base + AGGR_BATCH; if (nend > NN) nend = NN;

        for (int n = base; n < nend; n++) {
            float svv = g_sv[n * HEADS + hh];
            int beg = g_off[n], cnt = g_deg[n];

            float acc0 = 0.f, acc1 = 0.f, dsum = 0.f;
            if (cnt > 0) {
                int4 e0 = g_edge[beg];
                for (int it = 0; it < cnt; it++) {
                    int4 e1 = make_int4(0, 0, 0, 0);
                    if (it + 1 < cnt) e1 = g_edge[beg + it + 1];
                    int s = e0.x;
                    float fx = __int_as_float(e0.y), fy = __int_as_float(e0.z);
                    float sc = g_su[s * HEADS + hh] + svv + fmaf(fx, w2x, fmaf(fy, w2y, cc));
                    sc = fmaxf(sc, 0.2f * sc);       // LeakyReLU(0.2)
                    float tt = __expf(sc);
                    dsum += tt;
                    acc0 = fmaf(g_h[s * DIM + lane], tt, acc0);
                    acc1 = fmaf(g_h[s * DIM + 32 + lane], tt, acc1);
                    e0 = e1;
                }
            }
            float inv = 1.f / fmaxf(dsum, 1e-12f);
            g_aggr[n * DIM + lane]      = acc0 * inv;
            g_aggr[n * DIM + 32 + lane] = acc1 * inv;
            if (lane == 0) g_deg[n] = 0;   // zero-on-consume for next run
        }
    }
}

// ======== FFN via mma.sync tf32, two INDEPENDENT 256-thread halves per CTA ========
#define PA  68
#define PB2 260
#define OF_AH0 0
#define OF_AH1 (OF_AH0 + 128 * PA)
#define OF_B1  (OF_AH1 + 128 * PA)
#define OF_B2  (OF_B1 + 256 * PA)
#define OF_BV1 (OF_B2 + 64 * PB2)
#define OF_BV2 (OF_BV1 + 256)
#define SMF_TOTAL (OF_BV2 + 64)

#define MMA_TF32(c, a, b0v, b1v) \
    asm volatile("mma.sync.aligned.m16n8k8.row.col.f32.tf32.tf32.f32 " \
        "{%0,%1,%2,%3}, {%4,%5,%6,%7}, {%8,%9}, {%0,%1,%2,%3};" \
        : "+f"((c)[0]), "+f"((c)[1]), "+f"((c)[2]), "+f"((c)[3]) \
        : "r"((a)[0]), "r"((a)[1]), "r"((a)[2]), "r"((a)[3]), "r"(b0v), "r"(b1v))

#define BARH(id) asm volatile("bar.sync %0, %1;" :: "r"(id), "r"(256) : "memory")

__global__ __launch_bounds__(512, 1) void k_ffn_mma(
    const float* __restrict__ w1, const float* __restrict__ b1,
    const float* __restrict__ w2, const float* __restrict__ b2,
    float* __restrict__ out) {
    extern __shared__ float sm[];
    uint32_t* B1u = (uint32_t*)(sm + OF_B1);
    uint32_t* B2u = (uint32_t*)(sm + OF_B2);
    float* b1s = sm + OF_BV1;
    float* b2s = sm + OF_BV2;

    int t = threadIdx.x;
    int w = t >> 5, lane = t & 31;
    int gid = lane >> 2, tig = lane & 3;
    int half = w >> 3;
    int w8 = w & 7;
    int th = t & 255;
    int arow = w8 * 16 + gid;
    int barid = 1 + half;
    uint32_t* AHu = (uint32_t*)(sm + (half ? OF_AH1 : OF_AH0));

    if (t < 256) b1s[t] = b1[t];
    if (t < 64) b2s[t] = b2[t];
#pragma unroll
    for (int i = 0; i < 32; i++) {
        int idx = t + i * 512;
        int k = idx >> 8, n = idx & 255;
        B1u[n * PA + k] = to_tf32(w1[idx]);
    }
#pragma unroll
    for (int i = 0; i < 32; i++) {
        int idx = t + i * 512;
        int k = idx >> 6, n = idx & 63;
        B2u[n * PB2 + k] = to_tf32(w2[idx]);
    }
    __syncthreads();

    for (int tile = blockIdx.x * 2 + half; tile < NTILES; tile += gridDim.x * 2) {
        int n0 = tile * 128;
#pragma unroll
        for (int i = 0; i < 32; i++) {
            int idx = th + i * 256;
            int row = idx >> 6, kf = idx & 63;
            int node = n0 + row;
            float v = (node < NN) ? g_aggr[node * DIM + kf] : 0.f;
            AHu[row * PA + kf] = to_tf32(v);
        }
        BARH(barid);

        uint32_t af[8][4];
#pragma unroll
        for (int k = 0; k < 8; k++) {
            int base = arow * PA + k * 8 + tig;
            af[k][0] = AHu[base];
            af[k][1] = AHu[base + 8 * PA];
            af[k][2] = AHu[base + 4];
            af[k][3] = AHu[base + 8 * PA + 4];
        }
        BARH(barid);

        float c2[8][4];
#pragma unroll
        for (int nt = 0; nt < 8; nt++)
#pragma unroll
            for (int q = 0; q < 4; q++) c2[nt][q] = 0.f;

#pragma unroll
        for (int ch = 0; ch < 4; ch++) {
            int hc0 = ch * 64;
            float c1[8][4];
#pragma unroll
            for (int nt = 0; nt < 8; nt++)
#pragma unroll
                for (int q = 0; q < 4; q++) c1[nt][q] = 0.f;

#pragma unroll
            for (int nt = 0; nt < 8; nt++) {
                int nb = (hc0 + nt * 8 + gid) * PA + tig;
#pragma unroll
                for (int k = 0; k < 8; k++) {
                    uint32_t b0v = B1u[nb + k * 8];
                    uint32_t b1v = B1u[nb + k * 8 + 4];
                    MMA_TF32(c1[nt], af[k], b0v, b1v);
                }
            }
#pragma unroll
            for (int nt = 0; nt < 8; nt++) {
                int cl = nt * 8 + 2 * tig;
                int cg = hc0 + cl;
                float bb0 = b1s[cg], bb1 = b1s[cg + 1];
#pragma unroll
                for (int q = 0; q < 4; q++) {
                    int rr = arow + (q >> 1) * 8;
                    float v = c1[nt][q] + ((q & 1) ? bb1 : bb0);
                    v = 0.5f * v * (1.0f + erff(v * 0.70710678118654752f));
                    AHu[rr * PA + cl + (q & 1)] = to_tf32(v);
                }
            }
            BARH(barid);

#pragma unroll
            for (int k2 = 0; k2 < 8; k2++) {
                uint32_t a2[4];
                int base = arow * PA + k2 * 8 + tig;
                a2[0] = AHu[base];
                a2[1] = AHu[base + 8 * PA];
                a2[2] = AHu[base + 4];
                a2[3] = AHu[base + 8 * PA + 4];
#pragma unroll
                for (int nt = 0; nt < 8; nt++) {
                    int bb = (nt * 8 + gid) * PB2 + hc0 + k2 * 8 + tig;
                    uint32_t b0v = B2u[bb];
                    uint32_t b1v = B2u[bb + 4];
                    MMA_TF32(c2[nt], a2, b0v, b1v);
                }
            }
            BARH(barid);
        }

#pragma unroll
        for (int nt = 0; nt < 8; nt++) {
            int col = nt * 8 + 2 * tig;
            float bb0 = b2s[col], bb1 = b2s[col + 1];
            int nA = n0 + arow, nB = n0 + arow + 8;
            if (nA < NN) {
                float2 v = make_float2(c2[nt][0] + bb0, c2[nt][1] + bb1);
                *(float2*)(out + nA * DIM + col) = v;
            }
            if (nB < NN) {
                float2 v = make_float2(c2[nt][2] + bb0, c2[nt][3] + bb1);
                *(float2*)(out + nB * DIM + col) = v;
            }
        }
    }
}

extern "C" void kernel_launch(void* const* d_in, const int* in_sizes, int n_in,
                              void* d_out, int out_size) {
    const float* x       = (const float*)d_in[0];
    const float* ef      = (const float*)d_in[1];
    const float* w_in    = (const float*)d_in[2];
    const float* b_in    = (const float*)d_in[3];
    const float* w_edge  = (const float*)d_in[4];
    const float* b_edge  = (const float*)d_in[5];
    const float* w_att_u = (const float*)d_in[6];
    const float* b_att_u = (const float*)d_in[7];
    const float* w_att_v = (const float*)d_in[8];
    const float* w_att_e = (const float*)d_in[9];
    const float* b_att_e = (const float*)d_in[10];
    const float* w_ff1   = (const float*)d_in[11];
    const float* b_ff1   = (const float*)d_in[12];
    const float* w_ff2   = (const float*)d_in[13];
    const float* b_ff2   = (const float*)d_in[14];
    const int*   src     = (const int*)d_in[15];
    const int*   dst     = (const int*)d_in[16];
    float* out = (float*)d_out;

    cudaFuncSetAttribute(k_ffn_mma, cudaFuncAttributeMaxDynamicSharedMemorySize,
                         SMF_TOTAL * (int)sizeof(float));

    // one-time stream/event creation (host objects, not device memory)
    static cudaStream_t s_csr = nullptr;
    static cudaEvent_t ev_fork = nullptr, ev_join = nullptr;
    if (s_csr == nullptr) {
        cudaStreamCreateWithFlags(&s_csr, cudaStreamNonBlocking);
        cudaEventCreateWithFlags(&ev_fork, cudaEventDisableTiming);
        cudaEventCreateWithFlags(&ev_join, cudaEventDisableTiming);
    }

    // fork: CSR chain on s_csr (3 launches), node chain on stream 0
    cudaEventRecord(ev_fork, 0);
    cudaStreamWaitEvent(s_csr, ev_fork, 0);

    k_hist<<<1184, 256, 0, s_csr>>>(dst);
    k_scan_one<<<NB, 256, 0, s_csr>>>();
    k_scatter<<<1184, 256, 0, s_csr>>>(src, dst, ef);   // resets g_base_ctr + g_work
    cudaEventRecord(ev_join, s_csr);

    k_prep<<<1, 32>>>(w_edge, b_edge, w_att_e, b_att_e);
    k_node_in<<<2048, 256>>>(x, w_in, b_in, w_att_u, b_att_u, w_att_v);

    // join, then aggregate (dynamic work-stealing) + FFN
    cudaStreamWaitEvent(0, ev_join, 0);
    k_aggr<<<1184, 256>>>();
    k_ffn_mma<<<148, 512, SMF_TOTAL * sizeof(float)>>>(w_ff1, b_ff1, w_ff2, b_ff2, out);
}